// round 11
// baseline (speedup 1.0000x reference)
#include <cuda_runtime.h>
#include <cuda_fp16.h>
#include <cstdint>

// SeparableConv round 11:
//  k1 depthwise 16x8 tiles -> g_Y in MMA-FRAGMENT-MAJOR fp16 layout
//  k2 GEMM: A fragments loaded DIRECTLY global->registers (LDG.128),
//     no smem A, no cp.async, NO barrier in main loop. B smem-resident+permuted.
//
// g_Y layout: tile t (64 px) = 16KB at t*16384, 32 blocks of 512B,
//   block = kk*4 + (p>>4&3); lane l owns 16B = {a0,a1,a2,a3} of the
//   m16n8k16 A fragment (rows p&15, k cols kk*16..+15).

#define IMG_H 112
#define IMG_W 112
#define CIN   128
#define COUT  256
#define NIMG  32
#define NPIX  (NIMG * IMG_H * IMG_W)     // 401408

__device__ unsigned char g_Y[(size_t)NPIX * 256];

#define NT2   (NPIX / 64)                // 6272
#define GRID2 296

// k2 smem: B[256][136]f16 | bias
#define SM_B    0
#define SM_BIAS 69632
#define SM2_BYTES 70656
#define B_ROW_B 272

__device__ __forceinline__ uint32_t smem_u32(const void* p) {
    uint32_t a;
    asm("{ .reg .u64 t; cvta.to.shared.u64 t, %1; cvt.u32.u64 %0, t; }" : "=r"(a) : "l"(p));
    return a;
}
__device__ __forceinline__ void ldsm_x4(uint32_t* r, uint32_t addr) {
    asm volatile("ldmatrix.sync.aligned.m8n8.x4.shared.b16 {%0,%1,%2,%3}, [%4];"
                 : "=r"(r[0]), "=r"(r[1]), "=r"(r[2]), "=r"(r[3]) : "r"(addr));
}
__device__ __forceinline__ void mma16816(float* d, const uint32_t* a,
                                         const uint32_t* b, const float* c) {
    asm volatile(
        "mma.sync.aligned.m16n8k16.row.col.f32.f16.f16.f32 "
        "{%0,%1,%2,%3}, {%4,%5,%6,%7}, {%8,%9}, {%10,%11,%12,%13};"
        : "=f"(d[0]), "=f"(d[1]), "=f"(d[2]), "=f"(d[3])
        : "r"(a[0]), "r"(a[1]), "r"(a[2]), "r"(a[3]),
          "r"(b[0]), "r"(b[1]),
          "f"(c[0]), "f"(c[1]), "f"(c[2]), "f"(c[3]));
}
__device__ __forceinline__ float4 fma4(float4 a, float4 b, float4 c) {
    c.x = fmaf(a.x, b.x, c.x); c.y = fmaf(a.y, b.y, c.y);
    c.z = fmaf(a.z, b.z, c.z); c.w = fmaf(a.w, b.w, c.w);
    return c;
}
__device__ __forceinline__ void stcs_f4(float* p, float4 v) {
    asm volatile("st.global.cs.v4.f32 [%0], {%1,%2,%3,%4};"
                 :: "l"(p), "f"(v.x), "f"(v.y), "f"(v.z), "f"(v.w) : "memory");
}
__device__ __forceinline__ void stcs_u32(void* p, uint32_t v) {
    asm volatile("st.global.cs.u32 [%0], %1;" :: "l"(p), "r"(v) : "memory");
}

// ======================= k1: depthwise -> fragment-major scratch =============
__global__ __launch_bounds__(256, 2)
void dw_kernel(const float* __restrict__ x,
               const float* __restrict__ dwk,
               const float* __restrict__ dwb) {
    const int lane = threadIdx.x & 31;
    const int cp   = threadIdx.x >> 5;     // column pair 0..7
    const int c4 = lane;                   // channels 4*c4..+3
    const int tx0 = blockIdx.x * 16;
    const int ty0 = blockIdx.y * 8;
    const int n   = blockIdx.z;

    // invariant part of the fragment offset for this thread's channels
    const uint32_t kkterm = (uint32_t)(c4 >> 2) * 2048
                          + (uint32_t)(c4 & 1) * 32
                          + (uint32_t)((c4 >> 1) & 1) * 8;

    float4 w4[9];
    #pragma unroll
    for (int t = 0; t < 9; t++) w4[t] = *(const float4*)(dwk + t * CIN + c4 * 4);
    const float4 b4 = *(const float4*)(dwb + c4 * 4);

    const float* xp = x + (size_t)n * (IMG_H * IMG_W * CIN) + c4 * 4;
    const int gxb = tx0 + 2 * cp - 1;
    const int rowbase = (n * IMG_H + ty0) * IMG_W + tx0 + 2 * cp;

    float4 win[3][4];
    #pragma unroll
    for (int r = 0; r < 10; r++) {
        const int gy = ty0 - 1 + r;
        const bool oky = (unsigned)gy < IMG_H;
        #pragma unroll
        for (int dj = 0; dj < 4; dj++) {
            const int gx = gxb + dj;
            float4 v = make_float4(0.f, 0.f, 0.f, 0.f);
            if (oky && ((unsigned)gx < IMG_W))
                v = *(const float4*)(xp + ((size_t)(gy * IMG_W + gx)) * CIN);
            win[r % 3][dj] = v;
        }
        if (r >= 2) {
            float4 y0 = b4, y1 = b4;
            #pragma unroll
            for (int di = 0; di < 3; di++) {
                const float4* rw = win[(r - 2 + di) % 3];
                #pragma unroll
                for (int dj = 0; dj < 3; dj++) {
                    y0 = fma4(w4[di * 3 + dj], rw[dj],     y0);
                    y1 = fma4(w4[di * 3 + dj], rw[dj + 1], y1);
                }
            }
            const int p0 = rowbase + (r - 2) * IMG_W;
            // pixel p0 (cols 2cp) and p0+1
            #pragma unroll
            for (int e = 0; e < 2; e++) {
                const float4 y = e ? y1 : y0;
                const int p = p0 + e;
                __half2 hA = __floats2half2_rn(y.x, y.y);   // ch 4c4, 4c4+1
                __half2 hB = __floats2half2_rn(y.z, y.w);   // ch 4c4+2, 4c4+3
                size_t off = ((size_t)(p >> 6)) * 16384
                           + (uint32_t)((p >> 4) & 3) * 512
                           + (uint32_t)(p & 7) * 64
                           + (uint32_t)((p >> 3) & 1) * 4
                           + kkterm;
                stcs_u32(g_Y + off,      *(uint32_t*)&hA);
                stcs_u32(g_Y + off + 16, *(uint32_t*)&hB);
            }
        }
    }
}

// ======================= k2: barrier-free GEMM ===============================
extern __shared__ unsigned char smem[];

__global__ __launch_bounds__(256, 2)
void gemm_kernel(const float* __restrict__ pwk,
                 const float* __restrict__ pwb,
                 float* __restrict__ out) {
    const int tid  = threadIdx.x;
    const int lane = tid & 31;
    const int wid  = tid >> 5;

    const uint32_t s0  = smem_u32(smem);
    const uint32_t B_a = s0 + SM_B;

    __half* Bs   = (__half*)(smem + SM_B);
    float*  bias = (float*)(smem + SM_BIAS);

    // prologue: bias + permuted B(fp16)
    for (int i = tid; i < COUT; i += 256) bias[i] = pwb[i];
    for (int i = tid; i < CIN * COUT; i += 256) {
        int k = i >> 8;
        int n = i & 255;
        int seg = n & 192;
        int q   = n & 63;
        int row = seg + ((q & 15) >> 1) * 8 + (q >> 4) * 2 + (q & 1);
        Bs[row * 136 + k] = __float2half_rn(pwk[k * 256 + n]);
    }
    __syncthreads();     // only barrier in the kernel

    const int wm = wid >> 2, wn = wid & 3;   // warp tile 32(M) x 64(N)
    const int n0 = wn * 64;
    const int g  = lane & 3;
    const int rr = lane >> 2;

    const uint32_t addrB0 = B_a + (uint32_t)(n0 + (lane & 7) + ((lane & 16) >> 1)) * B_ROW_B
                                + ((lane & 8) << 1);

    // per-thread bias fragments (registers; frees per-tile LDS)
    float2 bini[8];
    #pragma unroll
    for (int k = 0; k < 4; k++) {
        bini[2*k].x   = bias[n0 + g * 16 + k * 4 + 0];
        bini[2*k].y   = bias[n0 + g * 16 + k * 4 + 1];
        bini[2*k+1].x = bias[n0 + g * 16 + k * 4 + 2];
        bini[2*k+1].y = bias[n0 + g * 16 + k * 4 + 3];
    }

    for (int t = blockIdx.x; t < NT2; t += GRID2) {
        // A fragments: base for (wm, mi, kk) = t*16384 + (kk*4 + wm*2 + mi)*512 + lane*16
        const uint4* Ab = (const uint4*)(g_Y + (size_t)t * 16384
                                              + (uint32_t)(wm * 2) * 512) + lane;
        // stride in uint4 units: mi -> +32, kk -> +128

        uint4 af[2][2];                      // [pipe][mi]
        af[0][0] = Ab[0];
        af[0][1] = Ab[32];

        float acc[2][8][4];
        #pragma unroll
        for (int mi = 0; mi < 2; mi++)
            #pragma unroll
            for (int nj = 0; nj < 8; nj++) {
                acc[mi][nj][0] = bini[nj].x; acc[mi][nj][1] = bini[nj].y;
                acc[mi][nj][2] = bini[nj].x; acc[mi][nj][3] = bini[nj].y;
            }

        #pragma unroll
        for (int kk = 0; kk < 8; kk++) {
            const int cur = kk & 1;
            if (kk < 7) {
                af[cur ^ 1][0] = Ab[(kk + 1) * 128];
                af[cur ^ 1][1] = Ab[(kk + 1) * 128 + 32];
            }
            uint32_t aB = addrB0 + (uint32_t)kk * 32;
            uint32_t bfr[4][4];
            #pragma unroll
            for (int j = 0; j < 4; j++) ldsm_x4(bfr[j], aB + (uint32_t)j * 16 * B_ROW_B);
            const uint32_t* a0 = (const uint32_t*)&af[cur][0];
            const uint32_t* a1 = (const uint32_t*)&af[cur][1];
            #pragma unroll
            for (int j = 0; j < 4; j++) {
                mma16816(acc[0][2*j],   a0, &bfr[j][0], acc[0][2*j]);
                mma16816(acc[0][2*j+1], a0, &bfr[j][2], acc[0][2*j+1]);
                mma16816(acc[1][2*j],   a1, &bfr[j][0], acc[1][2*j]);
                mma16816(acc[1][2*j+1], a1, &bfr[j][2], acc[1][2*j+1]);
            }
        }

        // epilogue: rows t*64 + (wm*2+mi)*16 + rr (+8), contiguous float4
        #pragma unroll
        for (int mi = 0; mi < 2; mi++) {
            int r0 = wm * 32 + mi * 16 + rr;
            int r1 = r0 + 8;
            float* o0 = out + ((size_t)t * 64 + r0) * COUT + n0 + g * 16;
            float* o1 = out + ((size_t)t * 64 + r1) * COUT + n0 + g * 16;
            #pragma unroll
            for (int k = 0; k < 4; k++) {
                float4 v0, v1;
                v0.x = acc[mi][2*k][0];   v0.y = acc[mi][2*k][1];
                v0.z = acc[mi][2*k+1][0]; v0.w = acc[mi][2*k+1][1];
                v1.x = acc[mi][2*k][2];   v1.y = acc[mi][2*k][3];
                v1.z = acc[mi][2*k+1][2]; v1.w = acc[mi][2*k+1][3];
                stcs_f4(o0 + k * 4, v0);
                stcs_f4(o1 + k * 4, v1);
            }
        }
    }
}

// ======================= launch =======================
extern "C" void kernel_launch(void* const* d_in, const int* in_sizes, int n_in,
                              void* d_out, int out_size) {
    const float* x   = (const float*)d_in[0];
    const float* dwk = (const float*)d_in[1];
    const float* dwb = (const float*)d_in[2];
    const float* pwk = (const float*)d_in[3];
    const float* pwb = (const float*)d_in[4];
    float* out = (float*)d_out;

    static bool init = false;
    if (!init) {
        cudaFuncSetAttribute(gemm_kernel,
                             cudaFuncAttributeMaxDynamicSharedMemorySize, SM2_BYTES);
        init = true;
    }

    dim3 g1(IMG_W / 16, IMG_H / 8, NIMG);
    dw_kernel<<<g1, 256>>>(x, dwk, dwb);
    gemm_kernel<<<GRID2, 256, SM2_BYTES>>>(pwk, pwb, out);
}

// round 12
// speedup vs baseline: 1.0602x; 1.0602x over previous
#include <cuda_runtime.h>
#include <cuda_fp16.h>
#include <cstdint>

// SeparableConv round 12:
//  k1 depthwise 16x8 tiles (r10, verified) -> g_Y fp16 [pixel][128ch]
//  k2 GEMM: ONE 512-thread CTA/SM, tile=128px, warp grid 4Mx4N (32x64/warp),
//     B smem-resident once, 4 A-buffers, depth-3 cp.async prefetch,
//     single barrier per tile, st.global.cs epilogue.

#define IMG_H 112
#define IMG_W 112
#define CIN   128
#define COUT  256
#define NIMG  32
#define NPIX  (NIMG * IMG_H * IMG_W)     // 401408

__device__ unsigned char g_Y[(size_t)NPIX * 256];

#define NT2   (NPIX / 128)               // 3136 tiles of 128 px
#define GRID2 148

// k2 smem: B[256][136]f16 | bias | A x4 [128][136]f16
#define SM_B    0
#define SM_BIAS 69632
#define SM_A    70656
#define A_BUF_B 34816                    // 128*272
#define SM2_BYTES (SM_A + 4 * A_BUF_B)   // 209920
#define A_ROW_B 272
#define B_ROW_B 272

__device__ __forceinline__ uint32_t smem_u32(const void* p) {
    uint32_t a;
    asm("{ .reg .u64 t; cvta.to.shared.u64 t, %1; cvt.u32.u64 %0, t; }" : "=r"(a) : "l"(p));
    return a;
}
__device__ __forceinline__ void ldsm_x4(uint32_t* r, uint32_t addr) {
    asm volatile("ldmatrix.sync.aligned.m8n8.x4.shared.b16 {%0,%1,%2,%3}, [%4];"
                 : "=r"(r[0]), "=r"(r[1]), "=r"(r[2]), "=r"(r[3]) : "r"(addr));
}
__device__ __forceinline__ void mma16816(float* d, const uint32_t* a,
                                         const uint32_t* b, const float* c) {
    asm volatile(
        "mma.sync.aligned.m16n8k16.row.col.f32.f16.f16.f32 "
        "{%0,%1,%2,%3}, {%4,%5,%6,%7}, {%8,%9}, {%10,%11,%12,%13};"
        : "=f"(d[0]), "=f"(d[1]), "=f"(d[2]), "=f"(d[3])
        : "r"(a[0]), "r"(a[1]), "r"(a[2]), "r"(a[3]),
          "r"(b[0]), "r"(b[1]),
          "f"(c[0]), "f"(c[1]), "f"(c[2]), "f"(c[3]));
}
__device__ __forceinline__ float4 fma4(float4 a, float4 b, float4 c) {
    c.x = fmaf(a.x, b.x, c.x); c.y = fmaf(a.y, b.y, c.y);
    c.z = fmaf(a.z, b.z, c.z); c.w = fmaf(a.w, b.w, c.w);
    return c;
}
__device__ __forceinline__ void cp16(uint32_t dst, const void* src) {
    asm volatile("cp.async.cg.shared.global [%0], [%1], 16;"
                 :: "r"(dst), "l"(src) : "memory");
}
#define CP_COMMIT() asm volatile("cp.async.commit_group;" ::: "memory")
#define CP_WAIT2()  asm volatile("cp.async.wait_group 2;" ::: "memory")

__device__ __forceinline__ void stcs_f4(float* p, float4 v) {
    asm volatile("st.global.cs.v4.f32 [%0], {%1,%2,%3,%4};"
                 :: "l"(p), "f"(v.x), "f"(v.y), "f"(v.z), "f"(v.w) : "memory");
}
__device__ __forceinline__ void stcs_u2(void* p, uint2 v) {
    asm volatile("st.global.cs.v2.u32 [%0], {%1,%2};"
                 :: "l"(p), "r"(v.x), "r"(v.y) : "memory");
}

// ======================= k1: depthwise 16x8 -> fp16 scratch (r10) ============
__global__ __launch_bounds__(256, 2)
void dw_kernel(const float* __restrict__ x,
               const float* __restrict__ dwk,
               const float* __restrict__ dwb) {
    const int lane = threadIdx.x & 31;
    const int cp   = threadIdx.x >> 5;
    const int c4 = lane;
    const int tx0 = blockIdx.x * 16;
    const int ty0 = blockIdx.y * 8;
    const int n   = blockIdx.z;

    float4 w4[9];
    #pragma unroll
    for (int t = 0; t < 9; t++) w4[t] = *(const float4*)(dwk + t * CIN + c4 * 4);
    const float4 b4 = *(const float4*)(dwb + c4 * 4);

    const float* xp = x + (size_t)n * (IMG_H * IMG_W * CIN) + c4 * 4;
    const int gxb = tx0 + 2 * cp - 1;
    const int rowbase = (n * IMG_H + ty0) * IMG_W + tx0 + 2 * cp;

    float4 win[3][4];
    #pragma unroll
    for (int r = 0; r < 10; r++) {
        const int gy = ty0 - 1 + r;
        const bool oky = (unsigned)gy < IMG_H;
        #pragma unroll
        for (int dj = 0; dj < 4; dj++) {
            const int gx = gxb + dj;
            float4 v = make_float4(0.f, 0.f, 0.f, 0.f);
            if (oky && ((unsigned)gx < IMG_W))
                v = *(const float4*)(xp + ((size_t)(gy * IMG_W + gx)) * CIN);
            win[r % 3][dj] = v;
        }
        if (r >= 2) {
            float4 y0 = b4, y1 = b4;
            #pragma unroll
            for (int di = 0; di < 3; di++) {
                const float4* rw = win[(r - 2 + di) % 3];
                #pragma unroll
                for (int dj = 0; dj < 3; dj++) {
                    y0 = fma4(w4[di * 3 + dj], rw[dj],     y0);
                    y1 = fma4(w4[di * 3 + dj], rw[dj + 1], y1);
                }
            }
            const size_t px0 = (size_t)rowbase + (size_t)(r - 2) * IMG_W;
            __half2 h01 = __floats2half2_rn(y0.x, y0.y);
            __half2 h23 = __floats2half2_rn(y0.z, y0.w);
            stcs_u2(g_Y + px0 * 256 + c4 * 8,
                    make_uint2(*(uint32_t*)&h01, *(uint32_t*)&h23));
            __half2 g01 = __floats2half2_rn(y1.x, y1.y);
            __half2 g23 = __floats2half2_rn(y1.z, y1.w);
            stcs_u2(g_Y + (px0 + 1) * 256 + c4 * 8,
                    make_uint2(*(uint32_t*)&g01, *(uint32_t*)&g23));
        }
    }
}

// ======================= k2: GEMM 512 threads, deep pipeline =================
extern __shared__ unsigned char smem[];

__device__ __forceinline__ void prefetch_A(uint32_t A_dst, int t, int tid) {
    const unsigned char* src = g_Y + (size_t)t * 32768;   // 128 px * 256 B
    #pragma unroll
    for (int j = 0; j < 4; j++) {
        int i = tid + j * 512;          // 0..2047
        int row = i >> 4, ch = i & 15;
        cp16(A_dst + (uint32_t)row * A_ROW_B + ch * 16, src + row * 256 + ch * 16);
    }
    CP_COMMIT();
}

__global__ __launch_bounds__(512, 1)
void gemm_kernel(const float* __restrict__ pwk,
                 const float* __restrict__ pwb,
                 float* __restrict__ out) {
    const int tid  = threadIdx.x;
    const int lane = tid & 31;
    const int wid  = tid >> 5;         // 0..15

    const uint32_t s0  = smem_u32(smem);
    const uint32_t A_a = s0 + SM_A;
    const uint32_t B_a = s0 + SM_B;

    __half* Bs   = (__half*)(smem + SM_B);
    float*  bias = (float*)(smem + SM_BIAS);

    // initial A prefetches (independent of B region) — overlap with B permute
    #pragma unroll
    for (int d = 0; d < 3; d++) {
        int tp = blockIdx.x + d * GRID2;
        if (tp < NT2) prefetch_A(A_a + d * A_BUF_B, tp, tid);
    }

    // prologue: bias + permuted B(fp16)
    for (int i = tid; i < COUT; i += 512) bias[i] = pwb[i];
    for (int i = tid; i < CIN * COUT; i += 512) {
        int k = i >> 8;
        int n = i & 255;
        int seg = n & 192;
        int q   = n & 63;
        int row = seg + ((q & 15) >> 1) * 8 + (q >> 4) * 2 + (q & 1);
        Bs[row * 136 + k] = __float2half_rn(pwk[k * 256 + n]);
    }
    __syncthreads();

    // warp tiling: 4 (M) x 4 (N); warp tile 32 x 64 of the 128x256 CTA tile
    const int wm = wid >> 2, wn = wid & 3;
    const int m0 = wm * 32;
    const int n0 = wn * 64;
    const int g  = lane & 3;
    const int rr = lane >> 2;

    const uint32_t addrA0 = A_a + (uint32_t)(m0 + (lane & 15)) * A_ROW_B + (lane & 16);
    const uint32_t addrB0 = B_a + (uint32_t)(n0 + (lane & 7) + ((lane & 16) >> 1)) * B_ROW_B
                                + ((lane & 8) << 1);

    // bias fragments in registers
    float2 bini[8];
    #pragma unroll
    for (int k = 0; k < 4; k++) {
        bini[2*k].x   = bias[n0 + g * 16 + k * 4 + 0];
        bini[2*k].y   = bias[n0 + g * 16 + k * 4 + 1];
        bini[2*k+1].x = bias[n0 + g * 16 + k * 4 + 2];
        bini[2*k+1].y = bias[n0 + g * 16 + k * 4 + 3];
    }

    int it = 0;
    for (int t = blockIdx.x; t < NT2; t += GRID2, ++it) {
        const int buf = it & 3;
        CP_WAIT2();                 // oldest outstanding group (this buf) done
        __syncthreads();            // all warps finished iteration it-1

        // refill the buffer freed by iteration it-1 (used again at it+3)
        int tp = t + 3 * GRID2;
        if (tp < NT2) prefetch_A(A_a + ((it + 3) & 3) * A_BUF_B, tp, tid);

        // ---- MMA ----
        float acc[2][8][4];
        #pragma unroll
        for (int mi = 0; mi < 2; mi++)
            #pragma unroll
            for (int nj = 0; nj < 8; nj++) {
                acc[mi][nj][0] = bini[nj].x; acc[mi][nj][1] = bini[nj].y;
                acc[mi][nj][2] = bini[nj].x; acc[mi][nj][3] = bini[nj].y;
            }

        const uint32_t aAb = addrA0 + (uint32_t)buf * A_BUF_B;
        #pragma unroll
        for (int kk = 0; kk < 8; kk++) {
            uint32_t aB = addrB0 + (uint32_t)kk * 32;
            uint32_t bfr[4][4];
            #pragma unroll
            for (int j = 0; j < 4; j++) ldsm_x4(bfr[j], aB + (uint32_t)j * 16 * B_ROW_B);
            uint32_t aA = aAb + (uint32_t)kk * 32;
            uint32_t afr[2][4];
            ldsm_x4(afr[0], aA);
            ldsm_x4(afr[1], aA + 16 * A_ROW_B);
            #pragma unroll
            for (int j = 0; j < 4; j++) {
                mma16816(acc[0][2*j],   afr[0], &bfr[j][0], acc[0][2*j]);
                mma16816(acc[0][2*j+1], afr[0], &bfr[j][2], acc[0][2*j+1]);
                mma16816(acc[1][2*j],   afr[1], &bfr[j][0], acc[1][2*j]);
                mma16816(acc[1][2*j+1], afr[1], &bfr[j][2], acc[1][2*j+1]);
            }
        }

        // ---- epilogue: rows t*128 + m0 + mi*16 + rr (+8) ----
        #pragma unroll
        for (int mi = 0; mi < 2; mi++) {
            int r0 = m0 + mi * 16 + rr;
            int r1 = r0 + 8;
            float* o0 = out + ((size_t)t * 128 + r0) * COUT + n0 + g * 16;
            float* o1 = out + ((size_t)t * 128 + r1) * COUT + n0 + g * 16;
            #pragma unroll
            for (int k = 0; k < 4; k++) {
                float4 v0, v1;
                v0.x = acc[mi][2*k][0];   v0.y = acc[mi][2*k][1];
                v0.z = acc[mi][2*k+1][0]; v0.w = acc[mi][2*k+1][1];
                v1.x = acc[mi][2*k][2];   v1.y = acc[mi][2*k][3];
                v1.z = acc[mi][2*k+1][2]; v1.w = acc[mi][2*k+1][3];
                stcs_f4(o0 + k * 4, v0);
                stcs_f4(o1 + k * 4, v1);
            }
        }
    }
}

// ======================= launch =======================
extern "C" void kernel_launch(void* const* d_in, const int* in_sizes, int n_in,
                              void* d_out, int out_size) {
    const float* x   = (const float*)d_in[0];
    const float* dwk = (const float*)d_in[1];
    const float* dwb = (const float*)d_in[2];
    const float* pwk = (const float*)d_in[3];
    const float* pwb = (const float*)d_in[4];
    float* out = (float*)d_out;

    static bool init = false;
    if (!init) {
        cudaFuncSetAttribute(gemm_kernel,
                             cudaFuncAttributeMaxDynamicSharedMemorySize, SM2_BYTES);
        init = true;
    }

    dim3 g1(IMG_W / 16, IMG_H / 8, NIMG);
    dw_kernel<<<g1, 256>>>(x, dwk, dwb);
    gemm_kernel<<<GRID2, 512, SM2_BYTES>>>(pwk, pwb, out);
}

// round 13
// speedup vs baseline: 1.4215x; 1.3408x over previous
#include <cuda_runtime.h>
#include <cuda_fp16.h>
#include <cstdint>

// SeparableConv round 13 (= r10 + sector-dense epilogue):
//  B column permutation changed so each lane quad writes 64B CONTIGUOUS per
//  STG.128 (full 32B sectors) -> kills ~2x DRAM write amplification.
//  Mapping: phys col q (0..63 in 64-col segment) <-> smem row bits:
//    row = [(q>>4)*2 + ((q>>1)&1)]*8 + ((q>>2)&3)*2 + (q&1)
//  Epilogue: lane g writes cols n0 + k*16 + g*4 .. +3  (64B dense per quad).

#define IMG_H 112
#define IMG_W 112
#define CIN   128
#define COUT  256
#define NIMG  32
#define NPIX  (NIMG * IMG_H * IMG_W)     // 401408

__device__ unsigned char g_Y[(size_t)NPIX * 256];

#define NT2   (NPIX / 64)                // 6272
#define GRID2 296

#define SM_B    0
#define SM_BIAS 69632
#define SM_A    70656
#define A_BUF_B 17408
#define SM2_BYTES 105472
#define A_ROW_B 272
#define B_ROW_B 272

__device__ __forceinline__ uint32_t smem_u32(const void* p) {
    uint32_t a;
    asm("{ .reg .u64 t; cvta.to.shared.u64 t, %1; cvt.u32.u64 %0, t; }" : "=r"(a) : "l"(p));
    return a;
}
__device__ __forceinline__ void ldsm_x4(uint32_t* r, uint32_t addr) {
    asm volatile("ldmatrix.sync.aligned.m8n8.x4.shared.b16 {%0,%1,%2,%3}, [%4];"
                 : "=r"(r[0]), "=r"(r[1]), "=r"(r[2]), "=r"(r[3]) : "r"(addr));
}
__device__ __forceinline__ void mma16816(float* d, const uint32_t* a,
                                         const uint32_t* b, const float* c) {
    asm volatile(
        "mma.sync.aligned.m16n8k16.row.col.f32.f16.f16.f32 "
        "{%0,%1,%2,%3}, {%4,%5,%6,%7}, {%8,%9}, {%10,%11,%12,%13};"
        : "=f"(d[0]), "=f"(d[1]), "=f"(d[2]), "=f"(d[3])
        : "r"(a[0]), "r"(a[1]), "r"(a[2]), "r"(a[3]),
          "r"(b[0]), "r"(b[1]),
          "f"(c[0]), "f"(c[1]), "f"(c[2]), "f"(c[3]));
}
__device__ __forceinline__ float4 fma4(float4 a, float4 b, float4 c) {
    c.x = fmaf(a.x, b.x, c.x); c.y = fmaf(a.y, b.y, c.y);
    c.z = fmaf(a.z, b.z, c.z); c.w = fmaf(a.w, b.w, c.w);
    return c;
}
__device__ __forceinline__ void cp16(uint32_t dst, const void* src) {
    asm volatile("cp.async.cg.shared.global [%0], [%1], 16;"
                 :: "r"(dst), "l"(src) : "memory");
}
#define CP_COMMIT() asm volatile("cp.async.commit_group;" ::: "memory")
#define CP_WAIT0()  asm volatile("cp.async.wait_group 0;" ::: "memory")

__device__ __forceinline__ void stcs_f4(float* p, float4 v) {
    asm volatile("st.global.cs.v4.f32 [%0], {%1,%2,%3,%4};"
                 :: "l"(p), "f"(v.x), "f"(v.y), "f"(v.z), "f"(v.w) : "memory");
}
__device__ __forceinline__ void stcs_u2(void* p, uint2 v) {
    asm volatile("st.global.cs.v2.u32 [%0], {%1,%2};"
                 :: "l"(p), "r"(v.x), "r"(v.y) : "memory");
}

// ======================= k1: depthwise 16x8 -> fp16 scratch (r10) ============
__global__ __launch_bounds__(256, 2)
void dw_kernel(const float* __restrict__ x,
               const float* __restrict__ dwk,
               const float* __restrict__ dwb) {
    const int lane = threadIdx.x & 31;
    const int cp   = threadIdx.x >> 5;
    const int c4 = lane;
    const int tx0 = blockIdx.x * 16;
    const int ty0 = blockIdx.y * 8;
    const int n   = blockIdx.z;

    float4 w4[9];
    #pragma unroll
    for (int t = 0; t < 9; t++) w4[t] = *(const float4*)(dwk + t * CIN + c4 * 4);
    const float4 b4 = *(const float4*)(dwb + c4 * 4);

    const float* xp = x + (size_t)n * (IMG_H * IMG_W * CIN) + c4 * 4;
    const int gxb = tx0 + 2 * cp - 1;
    const int rowbase = (n * IMG_H + ty0) * IMG_W + tx0 + 2 * cp;

    float4 win[3][4];
    #pragma unroll
    for (int r = 0; r < 10; r++) {
        const int gy = ty0 - 1 + r;
        const bool oky = (unsigned)gy < IMG_H;
        #pragma unroll
        for (int dj = 0; dj < 4; dj++) {
            const int gx = gxb + dj;
            float4 v = make_float4(0.f, 0.f, 0.f, 0.f);
            if (oky && ((unsigned)gx < IMG_W))
                v = *(const float4*)(xp + ((size_t)(gy * IMG_W + gx)) * CIN);
            win[r % 3][dj] = v;
        }
        if (r >= 2) {
            float4 y0 = b4, y1 = b4;
            #pragma unroll
            for (int di = 0; di < 3; di++) {
                const float4* rw = win[(r - 2 + di) % 3];
                #pragma unroll
                for (int dj = 0; dj < 3; dj++) {
                    y0 = fma4(w4[di * 3 + dj], rw[dj],     y0);
                    y1 = fma4(w4[di * 3 + dj], rw[dj + 1], y1);
                }
            }
            const size_t px0 = (size_t)rowbase + (size_t)(r - 2) * IMG_W;
            __half2 h01 = __floats2half2_rn(y0.x, y0.y);
            __half2 h23 = __floats2half2_rn(y0.z, y0.w);
            stcs_u2(g_Y + px0 * 256 + c4 * 8,
                    make_uint2(*(uint32_t*)&h01, *(uint32_t*)&h23));
            __half2 g01 = __floats2half2_rn(y1.x, y1.y);
            __half2 g23 = __floats2half2_rn(y1.z, y1.w);
            stcs_u2(g_Y + (px0 + 1) * 256 + c4 * 8,
                    make_uint2(*(uint32_t*)&g01, *(uint32_t*)&g23));
        }
    }
}

// ======================= k2: GEMM (r10 + dense stores) =======================
extern __shared__ unsigned char smem[];

__device__ __forceinline__ void prefetch_A(uint32_t A_dst, int t, int tid) {
    const unsigned char* src = g_Y + (size_t)t * 16384;
    #pragma unroll
    for (int j = 0; j < 4; j++) {
        int i = tid + j * 256;
        int row = i >> 4, ch = i & 15;
        cp16(A_dst + (uint32_t)row * A_ROW_B + ch * 16, src + row * 256 + ch * 16);
    }
    CP_COMMIT();
}

__global__ __launch_bounds__(256, 2)
void gemm_kernel(const float* __restrict__ pwk,
                 const float* __restrict__ pwb,
                 float* __restrict__ out) {
    const int tid  = threadIdx.x;
    const int lane = tid & 31;
    const int wid  = tid >> 5;

    const uint32_t s0  = smem_u32(smem);
    const uint32_t A_a = s0 + SM_A;
    const uint32_t B_a = s0 + SM_B;

    __half* Bs   = (__half*)(smem + SM_B);
    float*  bias = (float*)(smem + SM_BIAS);

    for (int i = tid; i < COUT; i += 256) bias[i] = pwb[i];
    // NEW permutation: phys col q -> smem row
    //   nj = (q>>4)*2 + ((q>>1)&1), gq = (q>>2)&3, lo = q&1
    //   row = seg + nj*8 + gq*2 + lo
    for (int i = tid; i < CIN * COUT; i += 256) {
        int k = i >> 8;
        int n = i & 255;
        int seg = n & 192;
        int q   = n & 63;
        int row = seg + ((q >> 4) * 2 + ((q >> 1) & 1)) * 8 + (((q >> 2) & 3) * 2) + (q & 1);
        Bs[row * 136 + k] = __float2half_rn(pwk[k * 256 + n]);
    }

    const int wm = wid >> 2, wn = wid & 3;
    const int m0 = wm * 32;
    const int n0 = wn * 64;
    const int g  = lane & 3;
    const int rr = lane >> 2;

    const uint32_t addrA0 = A_a + (uint32_t)(m0 + (lane & 15)) * A_ROW_B + (lane & 16);
    const uint32_t addrB0 = B_a + (uint32_t)(n0 + (lane & 7) + ((lane & 16) >> 1)) * B_ROW_B
                                + ((lane & 8) << 1);

    if (blockIdx.x < NT2) prefetch_A(A_a, blockIdx.x, tid);

    uint32_t buf = 0;
    for (int t = blockIdx.x; t < NT2; t += GRID2) {
        CP_WAIT0();
        __syncthreads();

        int tn = t + GRID2;
        if (tn < NT2) prefetch_A(A_a + (buf ^ 1) * A_BUF_B, tn, tid);

        float acc[2][8][4];
        #pragma unroll
        for (int mi = 0; mi < 2; mi++)
            #pragma unroll
            for (int nj = 0; nj < 8; nj++)
                #pragma unroll
                for (int q = 0; q < 4; q++) acc[mi][nj][q] = 0.0f;

        const uint32_t aAb = addrA0 + buf * A_BUF_B;
        #pragma unroll
        for (int kk = 0; kk < 8; kk++) {
            uint32_t aB = addrB0 + (uint32_t)kk * 32;
            uint32_t bfr[4][4];
            #pragma unroll
            for (int j = 0; j < 4; j++) ldsm_x4(bfr[j], aB + (uint32_t)j * 16 * B_ROW_B);
            uint32_t aA = aAb + (uint32_t)kk * 32;
            uint32_t afr[2][4];
            ldsm_x4(afr[0], aA);
            ldsm_x4(afr[1], aA + 16 * A_ROW_B);
            #pragma unroll
            for (int j = 0; j < 4; j++) {
                mma16816(acc[0][2*j],   afr[0], &bfr[j][0], acc[0][2*j]);
                mma16816(acc[0][2*j+1], afr[0], &bfr[j][2], acc[0][2*j+1]);
                mma16816(acc[1][2*j],   afr[1], &bfr[j][0], acc[1][2*j]);
                mma16816(acc[1][2*j+1], afr[1], &bfr[j][2], acc[1][2*j+1]);
            }
        }

        // ---- epilogue: lane quad g writes 64B contiguous per STG ----
        // acc[mi][2k+b][0,1] -> cols n0 + k*16 + g*4 + 2b + {0,1}
        #pragma unroll
        for (int mi = 0; mi < 2; mi++) {
            int r0 = m0 + mi * 16 + rr;
            int r1 = r0 + 8;
            float* o0 = out + ((size_t)t * 64 + r0) * COUT + n0 + g * 4;
            float* o1 = out + ((size_t)t * 64 + r1) * COUT + n0 + g * 4;
            #pragma unroll
            for (int k = 0; k < 4; k++) {
                float4 bv = *(const float4*)(bias + n0 + k * 16 + g * 4);
                float4 v0, v1;
                v0.x = acc[mi][2*k][0]   + bv.x;
                v0.y = acc[mi][2*k][1]   + bv.y;
                v0.z = acc[mi][2*k+1][0] + bv.z;
                v0.w = acc[mi][2*k+1][1] + bv.w;
                v1.x = acc[mi][2*k][2]   + bv.x;
                v1.y = acc[mi][2*k][3]   + bv.y;
                v1.z = acc[mi][2*k+1][2] + bv.z;
                v1.w = acc[mi][2*k+1][3] + bv.w;
                stcs_f4(o0 + k * 16, v0);
                stcs_f4(o1 + k * 16, v1);
            }
        }

        buf ^= 1;
    }
}

// ======================= launch =======================
extern "C" void kernel_launch(void* const* d_in, const int* in_sizes, int n_in,
                              void* d_out, int out_size) {
    const float* x   = (const float*)d_in[0];
    const float* dwk = (const float*)d_in[1];
    const float* dwb = (const float*)d_in[2];
    const float* pwk = (const float*)d_in[3];
    const float* pwb = (const float*)d_in[4];
    float* out = (float*)d_out;

    static bool init = false;
    if (!init) {
        cudaFuncSetAttribute(gemm_kernel,
                             cudaFuncAttributeMaxDynamicSharedMemorySize, SM2_BYTES);
        init = true;
    }

    dim3 g1(IMG_W / 16, IMG_H / 8, NIMG);
    dw_kernel<<<g1, 256>>>(x, dwk, dwb);
    gemm_kernel<<<GRID2, 256, SM2_BYTES>>>(pwk, pwb, out);
}